// round 2
// baseline (speedup 1.0000x reference)
#include <cuda_runtime.h>
#include <math.h>

#define MAXB 2048

// scratch (no allocations allowed)
__device__ float g_M[MAXB * 45];     // per-batch 9x9 Gram upper triangle
__device__ float g_cand[MAXB * 21];  // R1(9), R2(9), t(3)

__device__ __forceinline__ void inv3x3(const float* __restrict__ K, float* Ki) {
    float a = K[0], b = K[1], c = K[2];
    float d = K[3], e = K[4], f = K[5];
    float g = K[6], h = K[7], i = K[8];
    float A =  (e * i - f * h);
    float Bc = -(d * i - f * g);
    float C =  (d * h - e * g);
    float det = a * A + b * Bc + c * C;
    float id = 1.0f / det;
    Ki[0] = A * id;             Ki[1] = (c * h - b * i) * id; Ki[2] = (b * f - c * e) * id;
    Ki[3] = Bc * id;            Ki[4] = (a * i - c * g) * id; Ki[5] = (c * d - a * f) * id;
    Ki[6] = C * id;             Ki[7] = (b * g - a * h) * id; Ki[8] = (a * e - b * d) * id;
}

// ---------------------------------------------------------------------------
// Kernel A: per-batch Gram matrix M = sum_n w * X X^T   (X = vec(x1 x0^T), 9)
// ---------------------------------------------------------------------------
__global__ __launch_bounds__(256) void k_accumM(
    const float* __restrict__ kpts0, const float* __restrict__ kpts1,
    const float* __restrict__ conf,  const float* __restrict__ K, int N)
{
    int b = blockIdx.x;
    float Ki0[9], Ki1[9];
    inv3x3(K + (size_t)b * 18, Ki0);
    inv3x3(K + (size_t)b * 18 + 9, Ki1);

    float acc[45];
#pragma unroll
    for (int m = 0; m < 45; ++m) acc[m] = 0.f;

    const float2* p0 = (const float2*)(kpts0 + (size_t)b * N * 2);
    const float2* p1 = (const float2*)(kpts1 + (size_t)b * N * 2);
    const float*  pw = conf + (size_t)b * N;

    for (int n = threadIdx.x; n < N; n += blockDim.x) {
        float2 u0 = p0[n];
        float2 u1 = p1[n];
        float  w  = pw[n];
        float x0[3], x1[3], X[9];
        x0[0] = Ki0[0] * u0.x + Ki0[1] * u0.y + Ki0[2];
        x0[1] = Ki0[3] * u0.x + Ki0[4] * u0.y + Ki0[5];
        x0[2] = Ki0[6] * u0.x + Ki0[7] * u0.y + Ki0[8];
        x1[0] = Ki1[0] * u1.x + Ki1[1] * u1.y + Ki1[2];
        x1[1] = Ki1[3] * u1.x + Ki1[4] * u1.y + Ki1[5];
        x1[2] = Ki1[6] * u1.x + Ki1[7] * u1.y + Ki1[8];
#pragma unroll
        for (int i = 0; i < 3; ++i)
#pragma unroll
            for (int j = 0; j < 3; ++j) X[3 * i + j] = x1[i] * x0[j];
#pragma unroll
        for (int i = 0; i < 9; ++i) {
            float wxi = w * X[i];
#pragma unroll
            for (int j = i; j < 9; ++j)
                acc[i * 9 - i * (i + 1) / 2 + j] += wxi * X[j];
        }
    }

    // block reduction of 45 values
    __shared__ float red[8][45];
    int lane = threadIdx.x & 31, wid = threadIdx.x >> 5;
#pragma unroll
    for (int m = 0; m < 45; ++m) {
#pragma unroll
        for (int o = 16; o > 0; o >>= 1)
            acc[m] += __shfl_xor_sync(0xffffffffu, acc[m], o);
    }
    if (lane == 0) {
#pragma unroll
        for (int m = 0; m < 45; ++m) red[wid][m] = acc[m];
    }
    __syncthreads();
    if (threadIdx.x < 45) {
        float s = 0.f;
        int nw = blockDim.x >> 5;
        for (int wd = 0; wd < nw; ++wd) s += red[wd][threadIdx.x];
        g_M[b * 45 + threadIdx.x] = s;
    }
}

// ---------------------------------------------------------------------------
// Kernel B: 9x9 symmetric eigendecomposition (warp Jacobi), 3x3 SVD, candidates
// ---------------------------------------------------------------------------
__global__ __launch_bounds__(32) void k_solve()
{
    int b = blockIdx.x;
    int t = threadIdx.x;
    __shared__ float A[81], V[81];

    for (int idx = t; idx < 81; idx += 32) {
        int i = idx / 9, j = idx % 9;
        int ii = min(i, j), jj = max(i, j);
        A[idx] = g_M[b * 45 + ii * 9 - ii * (ii + 1) / 2 + jj];
        V[idx] = (i == j) ? 1.f : 0.f;
    }
    __syncwarp();

    for (int sweep = 0; sweep < 14; ++sweep) {
        __syncwarp();
        // convergence check (all lanes read same smem -> uniform)
        float off = 0.f, dia = 0.f;
        for (int i = 0; i < 9; ++i) {
            float d = A[i * 9 + i];
            dia += d * d;
            for (int j = i + 1; j < 9; ++j) {
                float o = A[i * 9 + j];
                off += o * o;
            }
        }
        if (off <= 1e-18f * dia) break;

        for (int p = 0; p < 8; ++p) {
            for (int q = p + 1; q < 9; ++q) {
                __syncwarp();
                float app = A[p * 9 + p], aqq = A[q * 9 + q], apq = A[p * 9 + q];
                if (fabsf(apq) <= 1e-12f * (fabsf(app) + fabsf(aqq))) continue;
                float tau = (aqq - app) / (2.f * apq);
                float tt  = copysignf(1.f, tau) / (fabsf(tau) + sqrtf(1.f + tau * tau));
                float c   = 1.f / sqrtf(1.f + tt * tt);
                float s   = tt * c;
                __syncwarp();
                if (t < 9) {   // row phase: B = J^T A
                    float ap = A[p * 9 + t], aq = A[q * 9 + t];
                    A[p * 9 + t] = c * ap - s * aq;
                    A[q * 9 + t] = s * ap + c * aq;
                }
                __syncwarp();
                if (t < 9) {   // col phase: A = B J ; V = V J
                    float ap = A[t * 9 + p], aq = A[t * 9 + q];
                    A[t * 9 + p] = c * ap - s * aq;
                    A[t * 9 + q] = s * ap + c * aq;
                    float vp = V[t * 9 + p], vq = V[t * 9 + q];
                    V[t * 9 + p] = c * vp - s * vq;
                    V[t * 9 + q] = s * vp + c * vq;
                }
            }
        }
    }
    __syncwarp();

    if (t == 0) {
        // smallest eigenvalue index
        int mi = 0; float mv = A[0];
        for (int i = 1; i < 9; ++i) {
            float d = A[i * 9 + i];
            if (d < mv) { mv = d; mi = i; }
        }
        float E[3][3];
#pragma unroll
        for (int i = 0; i < 3; ++i)
#pragma unroll
            for (int j = 0; j < 3; ++j) E[i][j] = V[(3 * i + j) * 9 + mi];

        // G = E^T E
        float G[3][3];
#pragma unroll
        for (int i = 0; i < 3; ++i)
#pragma unroll
            for (int j = 0; j < 3; ++j) {
                float s = 0.f;
#pragma unroll
                for (int k = 0; k < 3; ++k) s += E[k][i] * E[k][j];
                G[i][j] = s;
            }
        float ev[3][3] = {{1.f,0.f,0.f},{0.f,1.f,0.f},{0.f,0.f,1.f}};

#define J3(P, Q, R) do {                                                      \
        float app = G[P][P], aqq = G[Q][Q], apq = G[P][Q];                    \
        if (fabsf(apq) > 1e-14f * (fabsf(app) + fabsf(aqq))) {                \
            float tau = (aqq - app) / (2.f * apq);                            \
            float tt  = copysignf(1.f, tau) / (fabsf(tau) + sqrtf(1.f + tau * tau)); \
            float c   = 1.f / sqrtf(1.f + tt * tt);                           \
            float s   = tt * c;                                               \
            float apr = G[P][R], aqr = G[Q][R];                               \
            G[P][P] = app - tt * apq; G[Q][Q] = aqq + tt * apq;               \
            G[P][Q] = 0.f; G[Q][P] = 0.f;                                     \
            G[P][R] = c * apr - s * aqr; G[R][P] = G[P][R];                   \
            G[Q][R] = s * apr + c * aqr; G[R][Q] = G[Q][R];                   \
            for (int kk = 0; kk < 3; ++kk) {                                  \
                float vp = ev[kk][P], vq = ev[kk][Q];                         \
                ev[kk][P] = c * vp - s * vq;                                  \
                ev[kk][Q] = s * vp + c * vq;                                  \
            }                                                                 \
        } } while (0)

#pragma unroll
        for (int sw = 0; sw < 10; ++sw) { J3(0, 1, 2); J3(0, 2, 1); J3(1, 2, 0); }
#undef J3

        // sort eigenvalues descending
        float l0 = G[0][0], l1 = G[1][1], l2 = G[2][2];
        int i0 = 0, i1 = 1, i2 = 2;
        if (l1 > l0) { float tm = l0; l0 = l1; l1 = tm; int ti = i0; i0 = i1; i1 = ti; }
        if (l2 > l0) { float tm = l0; l0 = l2; l2 = tm; int ti = i0; i0 = i2; i2 = ti; }
        if (l2 > l1) { float tm = l1; l1 = l2; l2 = tm; int ti = i1; i1 = i2; i2 = ti; }

        float v1[3], v2[3], v3[3];
#pragma unroll
        for (int k = 0; k < 3; ++k) { v1[k] = ev[k][i0]; v2[k] = ev[k][i1]; v3[k] = ev[k][i2]; }

        // U columns: u1 = norm(E v1); u2 = norm(E v2 orthogonalized); u3 = u1 x u2
        float u1[3], u2[3], u3[3];
#pragma unroll
        for (int i = 0; i < 3; ++i)
            u1[i] = E[i][0] * v1[0] + E[i][1] * v1[1] + E[i][2] * v1[2];
        {
            float nn = rsqrtf(u1[0]*u1[0] + u1[1]*u1[1] + u1[2]*u1[2]);
            u1[0] *= nn; u1[1] *= nn; u1[2] *= nn;
        }
#pragma unroll
        for (int i = 0; i < 3; ++i)
            u2[i] = E[i][0] * v2[0] + E[i][1] * v2[1] + E[i][2] * v2[2];
        {
            float d = u1[0]*u2[0] + u1[1]*u2[1] + u1[2]*u2[2];
            u2[0] -= d * u1[0]; u2[1] -= d * u1[1]; u2[2] -= d * u1[2];
            float nn = rsqrtf(u2[0]*u2[0] + u2[1]*u2[1] + u2[2]*u2[2]);
            u2[0] *= nn; u2[1] *= nn; u2[2] *= nn;
        }
        u3[0] = u1[1] * u2[2] - u1[2] * u2[1];
        u3[1] = u1[2] * u2[0] - u1[0] * u2[2];
        u3[2] = u1[0] * u2[1] - u1[1] * u2[0];

        // fix v3 sign so E ~ U diag(s1,s2,s3>=0) V^T is a valid SVD
        float Ev3[3];
#pragma unroll
        for (int i = 0; i < 3; ++i)
            Ev3[i] = E[i][0] * v3[0] + E[i][1] * v3[1] + E[i][2] * v3[2];
        float s3p = u3[0]*Ev3[0] + u3[1]*Ev3[1] + u3[2]*Ev3[2];
        if (s3p < 0.f) { v3[0] = -v3[0]; v3[1] = -v3[1]; v3[2] = -v3[2]; }

        // R1 = U W V^T = u2 v1^T - u1 v2^T + u3 v3^T ; R2 = -u2 v1^T + u1 v2^T + u3 v3^T
        float R1[9], R2[9];
#pragma unroll
        for (int i = 0; i < 3; ++i)
#pragma unroll
            for (int j = 0; j < 3; ++j) {
                float c3 = u3[i] * v3[j];
                R1[3 * i + j] =  u2[i] * v1[j] - u1[i] * v2[j] + c3;
                R2[3 * i + j] = -u2[i] * v1[j] + u1[i] * v2[j] + c3;
            }
        float d1 = R1[0]*(R1[4]*R1[8]-R1[5]*R1[7]) - R1[1]*(R1[3]*R1[8]-R1[5]*R1[6]) + R1[2]*(R1[3]*R1[7]-R1[4]*R1[6]);
        float d2 = R2[0]*(R2[4]*R2[8]-R2[5]*R2[7]) - R2[1]*(R2[3]*R2[8]-R2[5]*R2[6]) + R2[2]*(R2[3]*R2[7]-R2[4]*R2[6]);
        float sg1 = (d1 < 0.f) ? -1.f : 1.f;
        float sg2 = (d2 < 0.f) ? -1.f : 1.f;
        float* cd = g_cand + b * 21;
#pragma unroll
        for (int m = 0; m < 9; ++m) { cd[m] = R1[m] * sg1; cd[9 + m] = R2[m] * sg2; }
        cd[18] = u3[0]; cd[19] = u3[1]; cd[20] = u3[2];
    }
}

// ---------------------------------------------------------------------------
// Kernel C: cheirality scoring over all points + argmax + output assembly
// ---------------------------------------------------------------------------
__global__ __launch_bounds__(256) void k_score(
    const float* __restrict__ kpts0, const float* __restrict__ kpts1,
    const float* __restrict__ conf,  const float* __restrict__ tscale,
    const float* __restrict__ K, float* __restrict__ out, int N)
{
    int b = blockIdx.x;
    float Ki0[9], Ki1[9];
    inv3x3(K + (size_t)b * 18, Ki0);
    inv3x3(K + (size_t)b * 18 + 9, Ki1);

    const float* cd = g_cand + b * 21;
    float R1[9], R2[9], tv[3];
#pragma unroll
    for (int m = 0; m < 9; ++m) { R1[m] = cd[m]; R2[m] = cd[9 + m]; }
    tv[0] = cd[18]; tv[1] = cd[19]; tv[2] = cd[20];

    const float2* p0 = (const float2*)(kpts0 + (size_t)b * N * 2);
    const float2* p1 = (const float2*)(kpts1 + (size_t)b * N * 2);
    const float*  pw = conf + (size_t)b * N;

    float sc[4] = {0.f, 0.f, 0.f, 0.f};
    for (int n = threadIdx.x; n < N; n += blockDim.x) {
        float2 u0 = p0[n];
        float2 u1 = p1[n];
        float  w  = pw[n];
        float x0[3], x1[3];
        x0[0] = Ki0[0] * u0.x + Ki0[1] * u0.y + Ki0[2];
        x0[1] = Ki0[3] * u0.x + Ki0[4] * u0.y + Ki0[5];
        x0[2] = Ki0[6] * u0.x + Ki0[7] * u0.y + Ki0[8];
        x1[0] = Ki1[0] * u1.x + Ki1[1] * u1.y + Ki1[2];
        x1[1] = Ki1[3] * u1.x + Ki1[4] * u1.y + Ki1[5];
        x1[2] = Ki1[6] * u1.x + Ki1[7] * u1.y + Ki1[8];

        float bb = x1[0]*x1[0] + x1[1]*x1[1] + x1[2]*x1[2];
        float bt = x1[0]*tv[0] + x1[1]*tv[1] + x1[2]*tv[2];

        // candidate R1 (c = 0: +t, c = 1: -t)
        {
            float a0 = R1[0]*x0[0] + R1[1]*x0[1] + R1[2]*x0[2];
            float a1 = R1[3]*x0[0] + R1[4]*x0[1] + R1[5]*x0[2];
            float a2 = R1[6]*x0[0] + R1[7]*x0[1] + R1[8]*x0[2];
            float aa = a0*a0 + a1*a1 + a2*a2;
            float ab = a0*x1[0] + a1*x1[1] + a2*x1[2];
            float at = a0*tv[0] + a1*tv[1] + a2*tv[2];
            float n0 = -at * bb + ab * bt;   // sign(d0), det > 0
            float n1 =  aa * bt - ab * at;   // sign(d1)
            if (n0 > 0.f && n1 > 0.f) sc[0] += w;
            if (n0 < 0.f && n1 < 0.f) sc[1] += w;
        }
        // candidate R2 (c = 2: +t, c = 3: -t)
        {
            float a0 = R2[0]*x0[0] + R2[1]*x0[1] + R2[2]*x0[2];
            float a1 = R2[3]*x0[0] + R2[4]*x0[1] + R2[5]*x0[2];
            float a2 = R2[6]*x0[0] + R2[7]*x0[1] + R2[8]*x0[2];
            float aa = a0*a0 + a1*a1 + a2*a2;
            float ab = a0*x1[0] + a1*x1[1] + a2*x1[2];
            float at = a0*tv[0] + a1*tv[1] + a2*tv[2];
            float n0 = -at * bb + ab * bt;
            float n1 =  aa * bt - ab * at;
            if (n0 > 0.f && n1 > 0.f) sc[2] += w;
            if (n0 < 0.f && n1 < 0.f) sc[3] += w;
        }
    }

    __shared__ float red[8][4];
    int lane = threadIdx.x & 31, wid = threadIdx.x >> 5;
#pragma unroll
    for (int m = 0; m < 4; ++m) {
#pragma unroll
        for (int o = 16; o > 0; o >>= 1)
            sc[m] += __shfl_xor_sync(0xffffffffu, sc[m], o);
    }
    if (lane == 0) {
#pragma unroll
        for (int m = 0; m < 4; ++m) red[wid][m] = sc[m];
    }
    __syncthreads();

    if (threadIdx.x == 0) {
        float s[4];
        int nw = blockDim.x >> 5;
#pragma unroll
        for (int m = 0; m < 4; ++m) {
            float acc = 0.f;
            for (int wd = 0; wd < nw; ++wd) acc += red[wd][m];
            s[m] = acc;
        }
        int best = 0;
        for (int c = 1; c < 4; ++c) if (s[c] > s[best]) best = c;

        const float* R = (best < 2) ? R1 : R2;
        float sg = (best & 1) ? -1.f : 1.f;
        float ts = tscale[(size_t)b * 2];   // t_scale[:, 0]
        float t0 = sg * tv[0] * ts, t1 = sg * tv[1] * ts, t2 = sg * tv[2] * ts;

        float* o01 = out + (size_t)b * 32;
        float* o10 = o01 + 16;
        // T01
        o01[0]  = R[0]; o01[1]  = R[1]; o01[2]  = R[2]; o01[3]  = t0;
        o01[4]  = R[3]; o01[5]  = R[4]; o01[6]  = R[5]; o01[7]  = t1;
        o01[8]  = R[6]; o01[9]  = R[7]; o01[10] = R[8]; o01[11] = t2;
        o01[12] = 0.f;  o01[13] = 0.f;  o01[14] = 0.f;  o01[15] = 1.f;
        // T10 = inverse: [R^T, -R^T t]
        float ti0 = -(R[0] * t0 + R[3] * t1 + R[6] * t2);
        float ti1 = -(R[1] * t0 + R[4] * t1 + R[7] * t2);
        float ti2 = -(R[2] * t0 + R[5] * t1 + R[8] * t2);
        o10[0]  = R[0]; o10[1]  = R[3]; o10[2]  = R[6]; o10[3]  = ti0;
        o10[4]  = R[1]; o10[5]  = R[4]; o10[6]  = R[7]; o10[7]  = ti1;
        o10[8]  = R[2]; o10[9]  = R[5]; o10[10] = R[8]; o10[11] = ti2;
        o10[12] = 0.f;  o10[13] = 0.f;  o10[14] = 0.f;  o10[15] = 1.f;
    }
}

// ---------------------------------------------------------------------------
extern "C" void kernel_launch(void* const* d_in, const int* in_sizes, int n_in,
                              void* d_out, int out_size)
{
    const float* kpts0 = (const float*)d_in[0];
    const float* kpts1 = (const float*)d_in[1];
    const float* conf  = (const float*)d_in[2];
    const float* tsc   = (const float*)d_in[3];
    const float* K     = (const float*)d_in[4];
    // d_in[5] = gt_pose_0to1 (unused by reference output)

    int B = in_sizes[4] / 18;        // K: (B, 2, 3, 3)
    int N = in_sizes[2] / B;         // conf: (B, N, 1)

    k_accumM<<<B, 256>>>(kpts0, kpts1, conf, K, N);
    k_solve<<<B, 32>>>();
    k_score<<<B, 256>>>(kpts0, kpts1, conf, tsc, K, (float*)d_out, N);
}